// round 1
// baseline (speedup 1.0000x reference)
#include <cuda_runtime.h>
#include <cuda_bf16.h>
#include <cstdint>

// Problem constants
constexpr int Bb   = 2;
constexpr int Ss   = 2048;
constexpr int Cin  = 512;
constexpr int Cout = 768;
constexpr int KW   = 31;
constexpr int PAD  = 15;            // (KW-1)/2
constexpr int Gg   = 6;
constexpr int Dd   = Cout / Gg;     // 128
constexpr int SP   = Ss + 2 * PAD;  // 2078 padded rows per batch

// Scratch (allocation-free rule: __device__ globals)
__device__ float g_Q[Bb * Ss * Cout];        // q projections
__device__ float g_K[Bb * SP * Cout];        // padded k projections
__device__ float g_V[Bb * SP * Cout];        // padded v projections
__device__ float g_relT[KW * Cout];          // rel transposed to [K][OUT]

// ---------------------------------------------------------------------------
// Prep: transpose rel -> relT, zero the pad rows of g_K / g_V
// ---------------------------------------------------------------------------
__global__ void prep_kernel(const float* __restrict__ rel) {
    const int stride = gridDim.x * blockDim.x;
    int i = blockIdx.x * blockDim.x + threadIdx.x;

    // relT[kk*Cout + o] = rel[o*KW + kk]
    for (int t = i; t < KW * Cout; t += stride) {
        int kk = t / Cout;
        int o  = t - kk * Cout;
        g_relT[t] = rel[o * KW + kk];
    }

    // zero pad rows: per batch, rows [0,PAD) and [PAD+Ss, SP)
    const int padRows = 2 * PAD;                 // 30 per batch
    const int totZero = Bb * padRows * Cout;     // 2*30*768
    for (int t = i; t < totZero; t += stride) {
        int r = t / Cout;
        int c = t - r * Cout;
        int b  = r / padRows;
        int rr = r - b * padRows;
        int row = b * SP + (rr < PAD ? rr : (PAD + Ss + rr - PAD));
        g_K[row * Cout + c] = 0.0f;
        g_V[row * Cout + c] = 0.0f;
    }
}

// ---------------------------------------------------------------------------
// SGEMM: C[m,n] = sum_k x[m,k] * W[n,k]
// Tile 128x128x16, 256 threads, 8x8 per thread.
// grid = (Cout/128, M/128, 3); z selects {Q, K, V} weight & destination.
// ---------------------------------------------------------------------------
__global__ void __launch_bounds__(256) proj_gemm_kernel(
    const float* __restrict__ x,
    const float* __restrict__ Wq,
    const float* __restrict__ Wk,
    const float* __restrict__ Wv)
{
    __shared__ float As[16][128];
    __shared__ float Bs[16][128];

    const int mat = blockIdx.z;
    const float* __restrict__ W = (mat == 0) ? Wq : (mat == 1) ? Wk : Wv;

    const int bn = blockIdx.x * 128;
    const int bm = blockIdx.y * 128;
    const int tid = threadIdx.x;

    // load mapping: 256 threads x 8 floats = 2048 = 128 rows x 16 cols
    const int lr = tid >> 1;            // 0..127
    const int lc = (tid & 1) * 8;       // 0 or 8

    const float* Aptr = x + (size_t)(bm + lr) * Cin + lc;
    const float* Bptr = W + (size_t)(bn + lr) * Cin + lc;

    const int tm = (tid >> 4) * 8;      // 0..120
    const int tn = (tid & 15) * 8;      // 0..120

    float acc[8][8];
#pragma unroll
    for (int i = 0; i < 8; i++)
#pragma unroll
        for (int j = 0; j < 8; j++) acc[i][j] = 0.0f;

    for (int kt = 0; kt < Cin; kt += 16) {
        float4 a0 = *(const float4*)(Aptr + kt);
        float4 a1 = *(const float4*)(Aptr + kt + 4);
        float4 b0 = *(const float4*)(Bptr + kt);
        float4 b1 = *(const float4*)(Bptr + kt + 4);

        __syncthreads();
        As[lc + 0][lr] = a0.x; As[lc + 1][lr] = a0.y;
        As[lc + 2][lr] = a0.z; As[lc + 3][lr] = a0.w;
        As[lc + 4][lr] = a1.x; As[lc + 5][lr] = a1.y;
        As[lc + 6][lr] = a1.z; As[lc + 7][lr] = a1.w;
        Bs[lc + 0][lr] = b0.x; Bs[lc + 1][lr] = b0.y;
        Bs[lc + 2][lr] = b0.z; Bs[lc + 3][lr] = b0.w;
        Bs[lc + 4][lr] = b1.x; Bs[lc + 5][lr] = b1.y;
        Bs[lc + 6][lr] = b1.z; Bs[lc + 7][lr] = b1.w;
        __syncthreads();

#pragma unroll
        for (int k = 0; k < 16; k++) {
            float av[8], bv[8];
            *(float4*)(av)     = *(const float4*)&As[k][tm];
            *(float4*)(av + 4) = *(const float4*)&As[k][tm + 4];
            *(float4*)(bv)     = *(const float4*)&Bs[k][tn];
            *(float4*)(bv + 4) = *(const float4*)&Bs[k][tn + 4];
#pragma unroll
            for (int i = 0; i < 8; i++)
#pragma unroll
                for (int j = 0; j < 8; j++)
                    acc[i][j] = fmaf(av[i], bv[j], acc[i][j]);
        }
    }

    // write out
#pragma unroll
    for (int i = 0; i < 8; i++) {
        const int m = bm + tm + i;
        float* Cp;
        if (mat == 0) {
            Cp = g_Q + (size_t)m * Cout;
        } else {
            const int b = m >> 11;          // /2048
            const int s = m & 2047;
            float* base = (mat == 1) ? g_K : g_V;
            Cp = base + (size_t)(b * SP + s + PAD) * Cout;
        }
        float* dst = Cp + bn + tn;
        *(float4*)(dst)     = make_float4(acc[i][0], acc[i][1], acc[i][2], acc[i][3]);
        *(float4*)(dst + 4) = make_float4(acc[i][4], acc[i][5], acc[i][6], acc[i][7]);
    }
}

// ---------------------------------------------------------------------------
// Attention: one warp per (b, s, g). Block = 8 warps = 8 consecutive s for the
// same (b, g) so the 31-row k/v windows overlap within a block (L1 reuse).
// grid = (Ss/8, Gg, Bb), 256 threads.
// ---------------------------------------------------------------------------
__global__ void __launch_bounds__(256) attn_kernel(
    float* __restrict__ out, float* __restrict__ attnOut)
{
    const unsigned FULL = 0xffffffffu;
    const int warp = threadIdx.x >> 5;
    const int lane = threadIdx.x & 31;
    const int s = blockIdx.x * 8 + warp;
    const int g = blockIdx.y;
    const int b = blockIdx.z;

    const size_t qoff = (size_t)(b * Ss + s) * Cout + g * Dd + lane * 4;
    const float4 q = *(const float4*)(g_Q + qoff);

    const float* kbase = g_K + (size_t)(b * SP + s) * Cout + g * Dd + lane * 4;
    const float* vbase = g_V + (size_t)(b * SP + s) * Cout + g * Dd + lane * 4;
    const float* rbase = g_relT + g * Dd + lane * 4;

    float myE = -3.4e38f;
#pragma unroll
    for (int kk = 0; kk < KW; kk++) {
        const float4 kv = *(const float4*)(kbase + (size_t)kk * Cout);
        const float4 rv = *(const float4*)(rbase + (size_t)kk * Cout);
        float e = q.x * (kv.x + rv.x) + q.y * (kv.y + rv.y)
                + q.z * (kv.z + rv.z) + q.w * (kv.w + rv.w);
#pragma unroll
        for (int o = 16; o; o >>= 1) e += __shfl_xor_sync(FULL, e, o);
        if (lane == kk) myE = e;
    }

    // softmax across lanes 0..30 (lane kk holds energy kk)
    float m = myE;
#pragma unroll
    for (int o = 16; o; o >>= 1) m = fmaxf(m, __shfl_xor_sync(FULL, m, o));
    float p = (lane < KW) ? __expf(myE - m) : 0.0f;
    float sum = p;
#pragma unroll
    for (int o = 16; o; o >>= 1) sum += __shfl_xor_sync(FULL, sum, o);
    const float a = p / sum;

    if (lane < KW)
        attnOut[((size_t)(b * Ss + s) * Gg + g) * KW + lane] = a;

    // out[d] = sum_kk a_kk * v[s+kk, d]
    float4 acc = make_float4(0.f, 0.f, 0.f, 0.f);
#pragma unroll
    for (int kk = 0; kk < KW; kk++) {
        const float ak = __shfl_sync(FULL, a, kk);
        const float4 vv = *(const float4*)(vbase + (size_t)kk * Cout);
        acc.x = fmaf(ak, vv.x, acc.x);
        acc.y = fmaf(ak, vv.y, acc.y);
        acc.z = fmaf(ak, vv.z, acc.z);
        acc.w = fmaf(ak, vv.w, acc.w);
    }
    *(float4*)(out + qoff) = acc;
}

// ---------------------------------------------------------------------------
extern "C" void kernel_launch(void* const* d_in, const int* in_sizes, int n_in,
                              void* d_out, int out_size)
{
    const float* x   = (const float*)d_in[0];
    const float* Wq  = (const float*)d_in[1];
    const float* Wk  = (const float*)d_in[2];
    const float* Wv  = (const float*)d_in[3];
    const float* rel = (const float*)d_in[4];

    float* out  = (float*)d_out;                       // [B,S,OUT] fp32
    float* attn = out + (size_t)Bb * Ss * Cout;        // [B,S,G,K] fp32

    prep_kernel<<<64, 256>>>(rel);
    proj_gemm_kernel<<<dim3(Cout / 128, (Bb * Ss) / 128, 3), 256>>>(x, Wq, Wk, Wv);
    attn_kernel<<<dim3(Ss / 8, Gg, Bb), 256>>>(out, attn);
}

// round 2
// speedup vs baseline: 1.0487x; 1.0487x over previous
#include <cuda_runtime.h>
#include <cuda_bf16.h>
#include <cstdint>

// Problem constants
constexpr int Bb   = 2;
constexpr int Ss   = 2048;
constexpr int Cin  = 512;
constexpr int Cout = 768;
constexpr int KW   = 31;
constexpr int PAD  = 15;            // (KW-1)/2
constexpr int Gg   = 6;
constexpr int Dd   = Cout / Gg;     // 128
constexpr int SP   = Ss + 2 * PAD;  // 2078 padded rows per batch

typedef unsigned long long ull;

// Scratch (allocation-free rule: __device__ globals)
__device__ float g_Q[Bb * Ss * Cout];        // q projections
__device__ float g_K[Bb * SP * Cout];        // padded k projections
__device__ float g_V[Bb * SP * Cout];        // padded v projections
__device__ float g_relT[KW * Cout];          // rel transposed to [K][OUT]

// ---------------------------------------------------------------------------
// Packed fp32x2 helpers (Blackwell FFMA2 — only reachable via PTX)
// ---------------------------------------------------------------------------
__device__ __forceinline__ ull pack2(float lo, float hi) {
    ull r; asm("mov.b64 %0, {%1, %2};" : "=l"(r) : "f"(lo), "f"(hi)); return r;
}
__device__ __forceinline__ float2 unpack2(ull v) {
    float2 f; asm("mov.b64 {%0, %1}, %2;" : "=f"(f.x), "=f"(f.y) : "l"(v)); return f;
}
__device__ __forceinline__ void ffma2(ull& d, ull a, ull b) {
    asm("fma.rn.f32x2 %0, %1, %2, %3;" : "=l"(d) : "l"(a), "l"(b), "l"(d));
}

// ---------------------------------------------------------------------------
// Prep: transpose rel -> relT, zero the pad rows of g_K / g_V
// ---------------------------------------------------------------------------
__global__ void prep_kernel(const float* __restrict__ rel) {
    const int stride = gridDim.x * blockDim.x;
    int i = blockIdx.x * blockDim.x + threadIdx.x;

    for (int t = i; t < KW * Cout; t += stride) {
        int kk = t / Cout;
        int o  = t - kk * Cout;
        g_relT[t] = rel[o * KW + kk];
    }

    const int padRows = 2 * PAD;                 // 30 per batch
    const int totZero = Bb * padRows * Cout;
    for (int t = i; t < totZero; t += stride) {
        int r = t / Cout;
        int c = t - r * Cout;
        int b  = r / padRows;
        int rr = r - b * padRows;
        int row = b * SP + (rr < PAD ? rr : (PAD + Ss + rr - PAD));
        g_K[row * Cout + c] = 0.0f;
        g_V[row * Cout + c] = 0.0f;
    }
}

// ---------------------------------------------------------------------------
// SGEMM via packed fp32x2 FMA: C[m,n] = sum_k x[m,k] * W[n,k]
// Tile 128x128x16, 256 threads, 8x8 per thread (accumulated as 8x4 float2
// pairs along n). Double-buffered smem, register prefetch, one sync/tile.
// grid = (Cout/128, M/128, 3); z selects {Q, K, V} weight & destination.
// ---------------------------------------------------------------------------
__global__ void __launch_bounds__(256, 2) proj_gemm_kernel(
    const float* __restrict__ x,
    const float* __restrict__ Wq,
    const float* __restrict__ Wk,
    const float* __restrict__ Wv)
{
    __shared__ float As[2][16][128];
    __shared__ float Bs[2][16][128];

    const int mat = blockIdx.z;
    const float* __restrict__ W = (mat == 0) ? Wq : (mat == 1) ? Wk : Wv;

    const int bn = blockIdx.x * 128;
    const int bm = blockIdx.y * 128;
    const int tid = threadIdx.x;

    // load mapping: 256 threads x 8 floats = 2048 = 128 rows x 16 cols
    const int lr = tid >> 1;            // 0..127
    const int lc = (tid & 1) * 8;       // 0 or 8

    const float* Aptr = x + (size_t)(bm + lr) * Cin + lc;
    const float* Bptr = W + (size_t)(bn + lr) * Cin + lc;

    const int tm = (tid >> 4) * 8;      // 0..120
    const int tn = (tid & 15) * 8;      // 0..120

    ull acc2[8][4];
#pragma unroll
    for (int i = 0; i < 8; i++)
#pragma unroll
        for (int j = 0; j < 4; j++) acc2[i][j] = pack2(0.0f, 0.0f);

    // Prologue: load K-tile 0 into buffer 0
    float4 a0 = *(const float4*)(Aptr);
    float4 a1 = *(const float4*)(Aptr + 4);
    float4 b0 = *(const float4*)(Bptr);
    float4 b1 = *(const float4*)(Bptr + 4);
    As[0][lc + 0][lr] = a0.x; As[0][lc + 1][lr] = a0.y;
    As[0][lc + 2][lr] = a0.z; As[0][lc + 3][lr] = a0.w;
    As[0][lc + 4][lr] = a1.x; As[0][lc + 5][lr] = a1.y;
    As[0][lc + 6][lr] = a1.z; As[0][lc + 7][lr] = a1.w;
    Bs[0][lc + 0][lr] = b0.x; Bs[0][lc + 1][lr] = b0.y;
    Bs[0][lc + 2][lr] = b0.z; Bs[0][lc + 3][lr] = b0.w;
    Bs[0][lc + 4][lr] = b1.x; Bs[0][lc + 5][lr] = b1.y;
    Bs[0][lc + 6][lr] = b1.z; Bs[0][lc + 7][lr] = b1.w;
    __syncthreads();

    int buf = 0;
    for (int kt = 16; kt <= Cin; kt += 16) {
        const bool more = (kt < Cin);
        if (more) {
            a0 = *(const float4*)(Aptr + kt);
            a1 = *(const float4*)(Aptr + kt + 4);
            b0 = *(const float4*)(Bptr + kt);
            b1 = *(const float4*)(Bptr + kt + 4);
        }

#pragma unroll
        for (int k = 0; k < 16; k++) {
            float av[8];
            *(float4*)(av)     = *(const float4*)&As[buf][k][tm];
            *(float4*)(av + 4) = *(const float4*)&As[buf][k][tm + 4];
            ull b2[4];
            const ull* bp = (const ull*)&Bs[buf][k][tn];   // tn*4B is 8B-aligned
            b2[0] = bp[0]; b2[1] = bp[1]; b2[2] = bp[2]; b2[3] = bp[3];
#pragma unroll
            for (int i = 0; i < 8; i++) {
                const ull ad = pack2(av[i], av[i]);
                ffma2(acc2[i][0], ad, b2[0]);
                ffma2(acc2[i][1], ad, b2[1]);
                ffma2(acc2[i][2], ad, b2[2]);
                ffma2(acc2[i][3], ad, b2[3]);
            }
        }

        if (more) {
            const int nb = buf ^ 1;
            As[nb][lc + 0][lr] = a0.x; As[nb][lc + 1][lr] = a0.y;
            As[nb][lc + 2][lr] = a0.z; As[nb][lc + 3][lr] = a0.w;
            As[nb][lc + 4][lr] = a1.x; As[nb][lc + 5][lr] = a1.y;
            As[nb][lc + 6][lr] = a1.z; As[nb][lc + 7][lr] = a1.w;
            Bs[nb][lc + 0][lr] = b0.x; Bs[nb][lc + 1][lr] = b0.y;
            Bs[nb][lc + 2][lr] = b0.z; Bs[nb][lc + 3][lr] = b0.w;
            Bs[nb][lc + 4][lr] = b1.x; Bs[nb][lc + 5][lr] = b1.y;
            Bs[nb][lc + 6][lr] = b1.z; Bs[nb][lc + 7][lr] = b1.w;
            __syncthreads();
            buf = nb;
        }
    }

    // write out
#pragma unroll
    for (int i = 0; i < 8; i++) {
        const int m = bm + tm + i;
        float* Cp;
        if (mat == 0) {
            Cp = g_Q + (size_t)m * Cout;
        } else {
            const int b = m >> 11;          // /2048
            const int s = m & 2047;
            float* base = (mat == 1) ? g_K : g_V;
            Cp = base + (size_t)(b * SP + s + PAD) * Cout;
        }
        float* dst = Cp + bn + tn;
        const float2 c0 = unpack2(acc2[i][0]);
        const float2 c1 = unpack2(acc2[i][1]);
        const float2 c2 = unpack2(acc2[i][2]);
        const float2 c3 = unpack2(acc2[i][3]);
        *(float4*)(dst)     = make_float4(c0.x, c0.y, c1.x, c1.y);
        *(float4*)(dst + 4) = make_float4(c2.x, c2.y, c3.x, c3.y);
    }
}

// ---------------------------------------------------------------------------
// Attention: one warp per (b, s, g). Block = 8 warps = 8 consecutive s for the
// same (b, g) so the 31-row k/v windows overlap within a block (L1 reuse).
// grid = (Ss/8, Gg, Bb), 256 threads.
// ---------------------------------------------------------------------------
__global__ void __launch_bounds__(256) attn_kernel(
    float* __restrict__ out, float* __restrict__ attnOut)
{
    const unsigned FULL = 0xffffffffu;
    const int warp = threadIdx.x >> 5;
    const int lane = threadIdx.x & 31;
    const int s = blockIdx.x * 8 + warp;
    const int g = blockIdx.y;
    const int b = blockIdx.z;

    const size_t qoff = (size_t)(b * Ss + s) * Cout + g * Dd + lane * 4;
    const float4 q = *(const float4*)(g_Q + qoff);

    const float* kbase = g_K + (size_t)(b * SP + s) * Cout + g * Dd + lane * 4;
    const float* vbase = g_V + (size_t)(b * SP + s) * Cout + g * Dd + lane * 4;
    const float* rbase = g_relT + g * Dd + lane * 4;

    float myE = -3.4e38f;
#pragma unroll
    for (int kk = 0; kk < KW; kk++) {
        const float4 kv = *(const float4*)(kbase + (size_t)kk * Cout);
        const float4 rv = *(const float4*)(rbase + (size_t)kk * Cout);
        float e = q.x * (kv.x + rv.x) + q.y * (kv.y + rv.y)
                + q.z * (kv.z + rv.z) + q.w * (kv.w + rv.w);
#pragma unroll
        for (int o = 16; o; o >>= 1) e += __shfl_xor_sync(FULL, e, o);
        if (lane == kk) myE = e;
    }

    // softmax across lanes 0..30 (lane kk holds energy kk)
    float m = myE;
#pragma unroll
    for (int o = 16; o; o >>= 1) m = fmaxf(m, __shfl_xor_sync(FULL, m, o));
    float p = (lane < KW) ? __expf(myE - m) : 0.0f;
    float sum = p;
#pragma unroll
    for (int o = 16; o; o >>= 1) sum += __shfl_xor_sync(FULL, sum, o);
    const float a = p / sum;

    if (lane < KW)
        attnOut[((size_t)(b * Ss + s) * Gg + g) * KW + lane] = a;

    // out[d] = sum_kk a_kk * v[s+kk, d]
    float4 acc = make_float4(0.f, 0.f, 0.f, 0.f);
#pragma unroll
    for (int kk = 0; kk < KW; kk++) {
        const float ak = __shfl_sync(FULL, a, kk);
        const float4 vv = *(const float4*)(vbase + (size_t)kk * Cout);
        acc.x = fmaf(ak, vv.x, acc.x);
        acc.y = fmaf(ak, vv.y, acc.y);
        acc.z = fmaf(ak, vv.z, acc.z);
        acc.w = fmaf(ak, vv.w, acc.w);
    }
    *(float4*)(out + qoff) = acc;
}

// ---------------------------------------------------------------------------
extern "C" void kernel_launch(void* const* d_in, const int* in_sizes, int n_in,
                              void* d_out, int out_size)
{
    const float* x   = (const float*)d_in[0];
    const float* Wq  = (const float*)d_in[1];
    const float* Wk  = (const float*)d_in[2];
    const float* Wv  = (const float*)d_in[3];
    const float* rel = (const float*)d_in[4];

    float* out  = (float*)d_out;                       // [B,S,OUT] fp32
    float* attn = out + (size_t)Bb * Ss * Cout;        // [B,S,G,K] fp32

    prep_kernel<<<64, 256>>>(rel);
    proj_gemm_kernel<<<dim3(Cout / 128, (Bb * Ss) / 128, 3), 256>>>(x, Wq, Wk, Wv);
    attn_kernel<<<dim3(Ss / 8, Gg, Bb), 256>>>(out, attn);
}

// round 4
// speedup vs baseline: 1.2200x; 1.1634x over previous
#include <cuda_runtime.h>
#include <cuda_bf16.h>
#include <cstdint>

// Problem constants
constexpr int Bb   = 2;
constexpr int Ss   = 2048;
constexpr int Cin  = 512;
constexpr int Cout = 768;
constexpr int KW   = 31;
constexpr int PAD  = 15;            // (KW-1)/2
constexpr int Gg   = 6;
constexpr int Dd   = Cout / Gg;     // 128
constexpr int SP   = Ss + 2 * PAD;  // 2078
constexpr int Mtot = Bb * Ss;       // 4096

// Scratch (allocation-free rule: __device__ globals)
__device__ float g_Q[Bb * Ss * Cout];
__device__ float g_K[Bb * SP * Cout];
__device__ float g_V[Bb * SP * Cout];
__device__ float g_relT[KW * Cout];

// ---------------------------------------------------------------------------
// tf32 split + mma.sync helpers (sm_80+, valid at plain sm_100 target)
// ---------------------------------------------------------------------------
__device__ __forceinline__ void split_tf32(float v, uint32_t& hi, uint32_t& lo) {
    asm("cvt.rna.tf32.f32 %0, %1;" : "=r"(hi) : "f"(v));
    float r = v - __uint_as_float(hi);
    asm("cvt.rna.tf32.f32 %0, %1;" : "=r"(lo) : "f"(r));
}

__device__ __forceinline__ void mma_tf32(float* c, const uint32_t* a,
                                         const uint32_t* b) {
    asm volatile(
        "mma.sync.aligned.m16n8k8.row.col.f32.tf32.tf32.f32 "
        "{%0,%1,%2,%3}, {%4,%5,%6,%7}, {%8,%9}, {%0,%1,%2,%3};"
        : "+f"(c[0]), "+f"(c[1]), "+f"(c[2]), "+f"(c[3])
        : "r"(a[0]), "r"(a[1]), "r"(a[2]), "r"(a[3]),
          "r"(b[0]), "r"(b[1]));
}

// ---------------------------------------------------------------------------
// Prep: transpose rel -> relT, zero the pad rows of g_K / g_V
// ---------------------------------------------------------------------------
__global__ void prep_kernel(const float* __restrict__ rel) {
    const int stride = gridDim.x * blockDim.x;
    int i = blockIdx.x * blockDim.x + threadIdx.x;

    for (int t = i; t < KW * Cout; t += stride) {
        int kk = t / Cout;
        int o  = t - kk * Cout;
        g_relT[t] = rel[o * KW + kk];
    }

    const int padRows = 2 * PAD;
    const int totZero = Bb * padRows * Cout;
    for (int t = i; t < totZero; t += stride) {
        int r = t / Cout;
        int c = t - r * Cout;
        int b  = r / padRows;
        int rr = r - b * padRows;
        int row = b * SP + (rr < PAD ? rr : (PAD + Ss + rr - PAD));
        g_K[row * Cout + c] = 0.0f;
        g_V[row * Cout + c] = 0.0f;
    }
}

// ---------------------------------------------------------------------------
// tf32x3 GEMM via mma.sync: C[m,n] = sum_k x[m,k] * W[n,k], ~fp32 accuracy.
// CTA tile 128(M) x 64(N), K-chunk 16, double-buffered smem (fp32, single
// copy; tf32 split done in registers). 8 warps as 4(m) x 2(n), warp tile
// 32x32 = 2 m16-tiles x 4 n8-tiles. 3 split products per tile pair.
// grid = (Cout/64, Mtot/128, 3 mats), 256 threads.
// ---------------------------------------------------------------------------
__global__ void __launch_bounds__(256, 2) proj_gemm_mma(
    const float* __restrict__ x,
    const float* __restrict__ Wq,
    const float* __restrict__ Wk,
    const float* __restrict__ Wv)
{
    __shared__ float As[2][128][20];   // 16 K-floats + 4 pad (bank-conflict-free)
    __shared__ float Bs[2][64][20];

    const int mat = blockIdx.z;
    const float* __restrict__ W = (mat == 0) ? Wq : (mat == 1) ? Wk : Wv;
    const int bn = blockIdx.x * 64;
    const int bm = blockIdx.y * 128;
    const int tid  = threadIdx.x;
    const int wid  = tid >> 5;
    const int lane = tid & 31;
    const int wm = wid >> 1;            // 0..3 (32-row slab)
    const int wn = wid & 1;             // 0..1 (32-col slab)
    const int r4 = lane >> 2;           // 0..7
    const int c4 = lane & 3;            // 0..3

    // Global load mapping (per K-chunk of 16 floats):
    // A: 128 rows x 4 float4 = 512 float4 -> 2 per thread (rows t>>2, t>>2+64)
    // B:  64 rows x 4 float4 = 256 float4 -> 1 per thread
    const int grow = tid >> 2;          // 0..63
    const int gcol = (tid & 3) * 4;
    const float* Ag0 = x + (size_t)(bm + grow) * Cin + gcol;
    const float* Ag1 = x + (size_t)(bm + grow + 64) * Cin + gcol;
    const float* Bg  = W + (size_t)(bn + grow) * Cin + gcol;

    float acc[2][4][4];
#pragma unroll
    for (int mt = 0; mt < 2; mt++)
#pragma unroll
        for (int nt = 0; nt < 4; nt++)
#pragma unroll
            for (int e = 0; e < 4; e++) acc[mt][nt][e] = 0.0f;

    // Prologue: chunk 0 -> buffer 0
    float4 pa0 = *(const float4*)(Ag0);
    float4 pa1 = *(const float4*)(Ag1);
    float4 pb  = *(const float4*)(Bg);
    *(float4*)&As[0][grow][gcol]      = pa0;
    *(float4*)&As[0][grow + 64][gcol] = pa1;
    *(float4*)&Bs[0][grow][gcol]      = pb;
    __syncthreads();

    int buf = 0;
    for (int kt = 0; kt < 32; kt++) {
        if (kt < 31) {
            const int k0 = (kt + 1) * 16;
            pa0 = *(const float4*)(Ag0 + k0);
            pa1 = *(const float4*)(Ag1 + k0);
            pb  = *(const float4*)(Bg + k0);
        }

#pragma unroll
        for (int ks = 0; ks < 2; ks++) {
            uint32_t aH[2][4], aL[2][4], bH[4][2], bL[4][2];
#pragma unroll
            for (int mt = 0; mt < 2; mt++) {
                const float* ap = &As[buf][wm * 32 + mt * 16 + r4][ks * 8 + c4];
                split_tf32(ap[0],          aH[mt][0], aL[mt][0]);  // (r,   c)
                split_tf32(ap[8 * 20],     aH[mt][1], aL[mt][1]);  // (r+8, c)
                split_tf32(ap[4],          aH[mt][2], aL[mt][2]);  // (r,   c+4)
                split_tf32(ap[8 * 20 + 4], aH[mt][3], aL[mt][3]);  // (r+8, c+4)
            }
#pragma unroll
            for (int nt = 0; nt < 4; nt++) {
                const float* bp = &Bs[buf][wn * 32 + nt * 8 + r4][ks * 8 + c4];
                split_tf32(bp[0], bH[nt][0], bL[nt][0]);           // (k,   n)
                split_tf32(bp[4], bH[nt][1], bL[nt][1]);           // (k+4, n)
            }
#pragma unroll
            for (int mt = 0; mt < 2; mt++)
#pragma unroll
                for (int nt = 0; nt < 4; nt++) {
                    mma_tf32(acc[mt][nt], aH[mt], bH[nt]);   // hi*hi
                    mma_tf32(acc[mt][nt], aL[mt], bH[nt]);   // lo*hi
                    mma_tf32(acc[mt][nt], aH[mt], bL[nt]);   // hi*lo
                }
        }

        if (kt < 31) {
            const int nb = buf ^ 1;
            *(float4*)&As[nb][grow][gcol]      = pa0;
            *(float4*)&As[nb][grow + 64][gcol] = pa1;
            *(float4*)&Bs[nb][grow][gcol]      = pb;
            __syncthreads();
            buf = nb;
        }
    }

    // Epilogue: scatter accumulator fragments to g_Q / padded g_K / g_V.
#pragma unroll
    for (int mt = 0; mt < 2; mt++) {
        const int m = bm + wm * 32 + mt * 16 + r4;   // rows m and m+8
        float *row0, *row1;
        if (mat == 0) {
            row0 = g_Q + (size_t)m * Cout;
            row1 = g_Q + (size_t)(m + 8) * Cout;
        } else {
            float* base = (mat == 1) ? g_K : g_V;
            const int b0 = m >> 11, s0 = m & 2047;   // 16-row tiles never cross batch
            row0 = base + (size_t)(b0 * SP + s0 + PAD) * Cout;
            row1 = row0 + (size_t)8 * Cout;
        }
#pragma unroll
        for (int nt = 0; nt < 4; nt++) {
            const int n = bn + wn * 32 + nt * 8 + 2 * c4;
            *(float2*)(row0 + n) = make_float2(acc[mt][nt][0], acc[mt][nt][1]);
            *(float2*)(row1 + n) = make_float2(acc[mt][nt][2], acc[mt][nt][3]);
        }
    }
}

// ---------------------------------------------------------------------------
// Attention: one warp per (b, s, g); 8 consecutive s per block for L1 reuse.
// grid = (Ss/8, Gg, Bb), 256 threads.
// ---------------------------------------------------------------------------
__global__ void __launch_bounds__(256) attn_kernel(
    float* __restrict__ out, float* __restrict__ attnOut)
{
    const unsigned FULL = 0xffffffffu;
    const int warp = threadIdx.x >> 5;
    const int lane = threadIdx.x & 31;
    const int s = blockIdx.x * 8 + warp;
    const int g = blockIdx.y;
    const int b = blockIdx.z;

    const size_t qoff = (size_t)(b * Ss + s) * Cout + g * Dd + lane * 4;
    const float4 q = *(const float4*)(g_Q + qoff);

    const float* kbase = g_K + (size_t)(b * SP + s) * Cout + g * Dd + lane * 4;
    const float* vbase = g_V + (size_t)(b * SP + s) * Cout + g * Dd + lane * 4;
    const float* rbase = g_relT + g * Dd + lane * 4;

    float myE = -3.4e38f;
#pragma unroll
    for (int kk = 0; kk < KW; kk++) {
        const float4 kv = *(const float4*)(kbase + (size_t)kk * Cout);
        const float4 rv = *(const float4*)(rbase + (size_t)kk * Cout);
        float e = q.x * (kv.x + rv.x) + q.y * (kv.y + rv.y)
                + q.z * (kv.z + rv.z) + q.w * (kv.w + rv.w);
#pragma unroll
        for (int o = 16; o; o >>= 1) e += __shfl_xor_sync(FULL, e, o);
        if (lane == kk) myE = e;
    }

    float m = myE;
#pragma unroll
    for (int o = 16; o; o >>= 1) m = fmaxf(m, __shfl_xor_sync(FULL, m, o));
    float p = (lane < KW) ? __expf(myE - m) : 0.0f;
    float sum = p;
#pragma unroll
    for (int o = 16; o; o >>= 1) sum += __shfl_xor_sync(FULL, sum, o);
    const float a = p / sum;

    if (lane < KW)
        attnOut[((size_t)(b * Ss + s) * Gg + g) * KW + lane] = a;

    float4 acc = make_float4(0.f, 0.f, 0.f, 0.f);
#pragma unroll
    for (int kk = 0; kk < KW; kk++) {
        const float ak = __shfl_sync(FULL, a, kk);
        const float4 vv = *(const float4*)(vbase + (size_t)kk * Cout);
        acc.x = fmaf(ak, vv.x, acc.x);
        acc.y = fmaf(ak, vv.y, acc.y);
        acc.z = fmaf(ak, vv.z, acc.z);
        acc.w = fmaf(ak, vv.w, acc.w);
    }
    *(float4*)(out + qoff) = acc;
}

// ---------------------------------------------------------------------------
extern "C" void kernel_launch(void* const* d_in, const int* in_sizes, int n_in,
                              void* d_out, int out_size)
{
    const float* x   = (const float*)d_in[0];
    const float* Wq  = (const float*)d_in[1];
    const float* Wk  = (const float*)d_in[2];
    const float* Wv  = (const float*)d_in[3];
    const float* rel = (const float*)d_in[4];

    float* out  = (float*)d_out;                       // [B,S,OUT] fp32
    float* attn = out + (size_t)Bb * Ss * Cout;        // [B,S,G,K] fp32

    prep_kernel<<<64, 256>>>(rel);
    proj_gemm_mma<<<dim3(Cout / 64, Mtot / 128, 3), 256>>>(x, Wq, Wk, Wv);
    attn_kernel<<<dim3(Ss / 8, Gg, Bb), 256>>>(out, attn);
}